// round 15
// baseline (speedup 1.0000x reference)
#include <cuda_runtime.h>
#include <cuda_bf16.h>

// Scratch (no allocations allowed -> __device__ globals)
__device__ float g_LU[2][128 * 128];     // LU factors of (I - A/2), row-major
__device__ float g_QT[2][128 * 128];     // QT[m][j*128+i] = Q[j][i]
__device__ float g_table[4096 * 128];    // pathemb table for every position value

// Inter-block phase counters, 128B apart. Zero at load; reset each call by the
// last block through the exit counter -> replay-safe.
__device__ volatile unsigned g_flags[3 * 32];  // [0]=c1 lu, [32]=c2 solve, [64]=exit

#define LU_PITCH 129
#define NBLOCKS  128
#define TBL_SMEM_FLOATS (2 * 16384 + 2 * 2048)   // 144 KB dynamic

__device__ __forceinline__ void poll_ge(int idx, unsigned tgt) {
    while (g_flags[idx] < tgt) {}
}

// ---------------------------------------------------------------------------
// Mega preproc kernel: lean rank-4 LU (blk 0-1, 32 steps) -> solve (blk 0-15)
// -> table (all). 128 blocks, 1/SM (144KB smem), all resident -> spin-safe.
// ---------------------------------------------------------------------------
__global__ __launch_bounds__(512, 1) void mega_kernel(const float* __restrict__ X,
                                                      const float* __restrict__ identity) {
    extern __shared__ float sm[];
    // rank-4 LU staging (double-buffered): 4 pivot columns + 4 pivot rows
    __shared__ float C0[2][128], C1[2][128], C2[2][128], C3[2][128];
    __shared__ float R0[2][128], R1[2][128], R2[2][128], R3[2][128];
    __shared__ int   pv[2][16];

    const int blk  = blockIdx.x;
    const int t    = threadIdx.x;
    const int tr   = t & 31;          // lane
    const int w    = t >> 5;          // warp id (0..15): owns columns 8w..8w+7
    const unsigned FULL = 0xffffffffu;

    // ============== Phase 1: register-lean rank-4 LU (32 steps) =============
    if (blk < 2) {
        const int m = blk;
        const float* Xm = X + m * 128 * 128;
        float* Xs = sm;                                  // 128*129

        for (int idx = t; idx < 128 * 128; idx += 512)
            Xs[(idx >> 7) * LU_PITCH + (idx & 127)] = Xm[idx];
        __syncthreads();

        // init M = I - 0.5*(tril(X) - tril(X)^T)
        float reg[4][8];
#pragma unroll
        for (int s = 0; s < 4; s++) {
            const int r = tr + 32 * s;
#pragma unroll
            for (int q = 0; q < 8; q++) {
                const int c = 8 * w + q;
                float a = (r > c) ? Xs[r * LU_PITCH + c]
                        : ((r < c) ? -Xs[c * LU_PITCH + r] : 0.0f);
                reg[s][q] = ((r == c) ? 1.0f : 0.0f) - 0.5f * a;
            }
        }

        // stage pivot group 0 (cols 0-3, rows 0-3) into buffer 0
        if (w == 0) {
#pragma unroll
            for (int s = 0; s < 4; s++) {
                C0[0][tr + 32 * s] = reg[s][0];
                C1[0][tr + 32 * s] = reg[s][1];
                C2[0][tr + 32 * s] = reg[s][2];
                C3[0][tr + 32 * s] = reg[s][3];
            }
        }
        if (tr == 0) { for (int q = 0; q < 8; q++) R0[0][8 * w + q] = reg[0][q]; }
        if (tr == 1) { for (int q = 0; q < 8; q++) R1[0][8 * w + q] = reg[0][q]; }
        if (tr == 2) { for (int q = 0; q < 8; q++) R2[0][8 * w + q] = reg[0][q]; }
        if (tr == 3) { for (int q = 0; q < 8; q++) R3[0][8 * w + q] = reg[0][q]; }

        for (int kp = 0; kp < 32; kp++) {
            __syncthreads();
            const int p = kp & 1;
            const int k = 4 * kp;

            if (8 * w + 7 >= k) {                        // warp-uniform dead skip
                // ---- 4x4 pivot-block scalars (16 live, redundant per thread)
                const float p01 = R0[p][k+1], p02 = R0[p][k+2], p03 = R0[p][k+3];
                const float id0 = 1.0f / R0[p][k];
                const float t10 = R1[p][k] * id0;
                const float u11 = R1[p][k+1] - t10 * p01;
                const float u12 = R1[p][k+2] - t10 * p02;
                const float u13 = R1[p][k+3] - t10 * p03;
                const float id1 = 1.0f / u11;
                const float t20 = R2[p][k] * id0;
                const float t21 = (R2[p][k+1] - t20 * p01) * id1;
                const float u22 = (R2[p][k+2] - t20 * p02) - t21 * u12;
                const float u23 = (R2[p][k+3] - t20 * p03) - t21 * u13;
                const float id2 = 1.0f / u22;
                const float t30 = R3[p][k] * id0;
                const float t31 = (R3[p][k+1] - t30 * p01) * id1;
                const float t32 = ((R3[p][k+2] - t30 * p02) - t31 * u12) * id2;
                const float u33 = ((R3[p][k+3] - t30 * p03) - t31 * u13) - t32 * u23;
                const float id3 = 1.0f / u33;

                // ---- per-row multipliers, zeroed beyond the row's depth ----
                // For pivot rows k+1..k+3 the l-chain from C reproduces the
                // t-multipliers exactly, so ONE code path covers all rows.
                float m0[4], m1[4], m2[4], m3[4];
#pragma unroll
                for (int s = 0; s < 4; s++) {
                    const int r = tr + 32 * s;
                    const float c0 = C0[p][r], c1 = C1[p][r];
                    const float c2 = C2[p][r], c3 = C3[p][r];
                    const float l0 = c0 * id0;
                    const float l1 = (c1 - l0 * p01) * id1;
                    const float l2 = ((c2 - l0 * p02) - l1 * u12) * id2;
                    const float l3 = (((c3 - l0 * p03) - l1 * u13) - l2 * u23) * id3;
                    m0[s] = (r > k)     ? l0 : 0.0f;
                    m1[s] = (r > k + 1) ? l1 : 0.0f;
                    m2[s] = (r > k + 2) ? l2 : 0.0f;
                    m3[s] = (r > k + 3) ? l3 : 0.0f;
                }

                // ---- unified update, q-outer (u's are 4 transient scalars) --
#pragma unroll
                for (int q = 0; q < 8; q++) {
                    const int cc = 8 * w + q;
                    const float u1v = R0[p][cc];
                    const float u2v = R1[p][cc] - t10 * u1v;
                    const float u3v = (R2[p][cc] - t20 * u1v) - t21 * u2v;
                    const float u4v = ((R3[p][cc] - t30 * u1v) - t31 * u2v) - t32 * u3v;
#pragma unroll
                    for (int s = 0; s < 4; s++) {
                        const int r = tr + 32 * s;
                        if (r > k) {
                            if (cc >= k && cc <= k + 3 && cc < r) {
                                float v = m0[s];                 // L-multiplier store
                                if (cc == k + 1) v = m1[s];
                                if (cc == k + 2) v = m2[s];
                                if (cc == k + 3) v = m3[s];
                                reg[s][q] = v;
                            } else if (cc > k) {                 // Schur / U update
                                reg[s][q] -= m0[s] * u1v + m1[s] * u2v
                                           + m2[s] * u3v + m3[s] * u4v;
                            }
                        }
                    }
                }

                // ---- stage next pivot group (cols/rows k+4..k+7) ----
                if (kp < 31) {
                    const int kn = k + 4;
                    if (w == (kn >> 3)) {                // column owner warp
                        const int qn = kn & 7;           // 0 or 4
#pragma unroll
                        for (int s = 0; s < 4; s++) {
                            float v0, v1, v2, v3;
                            if (qn == 0) { v0 = reg[s][0]; v1 = reg[s][1]; v2 = reg[s][2]; v3 = reg[s][3]; }
                            else         { v0 = reg[s][4]; v1 = reg[s][5]; v2 = reg[s][6]; v3 = reg[s][7]; }
                            C0[p ^ 1][tr + 32 * s] = v0;
                            C1[p ^ 1][tr + 32 * s] = v1;
                            C2[p ^ 1][tr + 32 * s] = v2;
                            C3[p ^ 1][tr + 32 * s] = v3;
                        }
                    }
#pragma unroll
                    for (int i = 0; i < 4; i++) {
                        if (tr == ((kn + i) & 31)) {     // row kn+i owner lane
                            const int sn = (kn + i) >> 5;
#pragma unroll
                            for (int q = 0; q < 8; q++) {
                                float v = reg[0][q];
#pragma unroll
                                for (int ss = 1; ss < 4; ss++)
                                    if (ss == sn) v = reg[ss][q];
                                if (i == 0)      R0[p ^ 1][8 * w + q] = v;
                                else if (i == 1) R1[p ^ 1][8 * w + q] = v;
                                else if (i == 2) R2[p ^ 1][8 * w + q] = v;
                                else             R3[p ^ 1][8 * w + q] = v;
                            }
                        }
                    }
                }
            }
        }
        __syncthreads();
#pragma unroll
        for (int s = 0; s < 4; s++) {
            const int r = tr + 32 * s;
#pragma unroll
            for (int q = 0; q < 8; q++)
                Xs[r * LU_PITCH + 8 * w + q] = reg[s][q];
        }
        __syncthreads();
        for (int idx = t; idx < 128 * 128; idx += 512)
            g_LU[m][idx] = Xs[(idx >> 7) * LU_PITCH + (idx & 127)];
        __syncthreads();
        __threadfence();
        if (t == 0) atomicAdd((unsigned*)&g_flags[0], 1u);      // c1++
    }

    // =========================== Phase 2: solve =============================
    if (blk < 16) {
        if (t == 0) poll_ge(0, 2u);
        __syncthreads();
        __threadfence();

        const int m = blk >> 3;
        const int j = ((blk & 7) << 4) + w;              // 16 RHS per block
        const float* Xm  = X + m * 128 * 128;
        const float* LUg = g_LU[m];
        float* LUs   = sm;                               // 128*129
        float* rdiag = sm + 128 * LU_PITCH;              // 128

        for (int idx = t; idx < 128 * 128; idx += 512)
            LUs[(idx >> 7) * LU_PITCH + (idx & 127)] = LUg[idx];
        if (t < 128) rdiag[t] = 1.0f / LUg[t * 128 + t];
        __syncthreads();

        const int lane = tr;
        float y0, y1, y2, y3;
        {
            const int i0 = lane, i1 = lane + 32, i2 = lane + 64, i3 = lane + 96;
            float a0 = (i0 > j) ? Xm[i0 * 128 + j] : ((i0 < j) ? -Xm[j * 128 + i0] : 0.0f);
            float a1 = (i1 > j) ? Xm[i1 * 128 + j] : ((i1 < j) ? -Xm[j * 128 + i1] : 0.0f);
            float a2 = (i2 > j) ? Xm[i2 * 128 + j] : ((i2 < j) ? -Xm[j * 128 + i2] : 0.0f);
            float a3 = (i3 > j) ? Xm[i3 * 128 + j] : ((i3 < j) ? -Xm[j * 128 + i3] : 0.0f);
            y0 = ((i0 == j) ? 1.0f : 0.0f) + 0.5f * a0;
            y1 = ((i1 == j) ? 1.0f : 0.0f) + 0.5f * a1;
            y2 = ((i2 == j) ? 1.0f : 0.0f) + 0.5f * a2;
            y3 = ((i3 == j) ? 1.0f : 0.0f) + 0.5f * a3;
        }

        // forward: L z = r (unit lower)
#pragma unroll 4
        for (int kk = 0; kk < 32; kk++) {
            const float yk = __shfl_sync(FULL, y0, kk);
            const float* col = LUs + kk;
            if (lane > kk) y0 -= col[lane * LU_PITCH] * yk;
            y1 -= col[(lane + 32) * LU_PITCH] * yk;
            y2 -= col[(lane + 64) * LU_PITCH] * yk;
            y3 -= col[(lane + 96) * LU_PITCH] * yk;
        }
#pragma unroll 4
        for (int kk = 0; kk < 32; kk++) {
            const float yk = __shfl_sync(FULL, y1, kk);
            const float* col = LUs + 32 + kk;
            if (lane > kk) y1 -= col[(lane + 32) * LU_PITCH] * yk;
            y2 -= col[(lane + 64) * LU_PITCH] * yk;
            y3 -= col[(lane + 96) * LU_PITCH] * yk;
        }
#pragma unroll 4
        for (int kk = 0; kk < 32; kk++) {
            const float yk = __shfl_sync(FULL, y2, kk);
            const float* col = LUs + 64 + kk;
            if (lane > kk) y2 -= col[(lane + 64) * LU_PITCH] * yk;
            y3 -= col[(lane + 96) * LU_PITCH] * yk;
        }
#pragma unroll 4
        for (int kk = 0; kk < 31; kk++) {
            const float yk = __shfl_sync(FULL, y3, kk);
            if (lane > kk) y3 -= LUs[(lane + 96) * LU_PITCH + 96 + kk] * yk;
        }
        // backward: U q = z
#pragma unroll 4
        for (int kk = 31; kk >= 0; kk--) {
            const int k = 96 + kk;
            const float yk = __shfl_sync(FULL, y3, kk) * rdiag[k];
            if (lane == kk) y3 = yk;
            else if (lane < kk) y3 -= LUs[(lane + 96) * LU_PITCH + k] * yk;
            y0 -= LUs[lane * LU_PITCH + k] * yk;
            y1 -= LUs[(lane + 32) * LU_PITCH + k] * yk;
            y2 -= LUs[(lane + 64) * LU_PITCH + k] * yk;
        }
#pragma unroll 4
        for (int kk = 31; kk >= 0; kk--) {
            const int k = 64 + kk;
            const float yk = __shfl_sync(FULL, y2, kk) * rdiag[k];
            if (lane == kk) y2 = yk;
            else if (lane < kk) y2 -= LUs[(lane + 64) * LU_PITCH + k] * yk;
            y0 -= LUs[lane * LU_PITCH + k] * yk;
            y1 -= LUs[(lane + 32) * LU_PITCH + k] * yk;
        }
#pragma unroll 4
        for (int kk = 31; kk >= 0; kk--) {
            const int k = 32 + kk;
            const float yk = __shfl_sync(FULL, y1, kk) * rdiag[k];
            if (lane == kk) y1 = yk;
            else if (lane < kk) y1 -= LUs[(lane + 32) * LU_PITCH + k] * yk;
            y0 -= LUs[lane * LU_PITCH + k] * yk;
        }
#pragma unroll 4
        for (int kk = 31; kk >= 0; kk--) {
            const float yk = __shfl_sync(FULL, y0, kk) * rdiag[kk];
            if (lane == kk) y0 = yk;
            else if (lane < kk) y0 -= LUs[lane * LU_PITCH + kk] * yk;
        }
        float* dst = g_QT[m] + j * 128 + lane;
        dst[0] = y0; dst[32] = y1; dst[64] = y2; dst[96] = y3;

        __syncthreads();
        __threadfence();
        if (t == 0) atomicAdd((unsigned*)&g_flags[32], 1u);     // c2++
    }

    // =========================== Phase 3: table =============================
    if (t == 0) poll_ge(32, 16u);
    __syncthreads();
    __threadfence();

    {
        float* Q0s  = sm;
        float* Q1s  = sm + 16384;
        float* bufA = sm + 32768;
        float* bufB = sm + 34816;
        const int g = blk;
        const int l = t >> 7;
        const int j = t & 127;

        {
            const float4* src = (const float4*)g_QT;
            float4* dst = (float4*)sm;
            for (int i = t; i < 8192; i += 512) dst[i] = src[i];
        }
        if (t < 128) bufA[j] = identity[j];
        if (g == 0 && t < 128) {
            g_table[0 + j]   = identity[j];
            g_table[128 + j] = identity[j];
        }
        __syncthreads();

        float* cur = bufA;
        float* nxt = bufB;
        for (int d = 0; d < 7; d++) {                    // root path: levels 2..8
            if (t < 128) {
                const int b = (g >> d) & 1;
                const float* Qp = b ? Q1s : Q0s;
                float a0 = 0.f, a1 = 0.f, a2 = 0.f, a3 = 0.f;
#pragma unroll
                for (int i = 0; i < 128; i += 4) {
                    const float4 vv = *(const float4*)(cur + i);
                    a0 += vv.x * Qp[(i + 0) * 128 + j];
                    a1 += vv.y * Qp[(i + 1) * 128 + j];
                    a2 += vv.z * Qp[(i + 2) * 128 + j];
                    a3 += vv.w * Qp[(i + 3) * 128 + j];
                }
                const float acc = (a0 + a1) + (a2 + a3);
                nxt[j] = acc;
                const int p = (g & ((2 << d) - 1)) | (2 << d);
                g_table[p * 128 + j] = acc;
            }
            __syncthreads();
            float* tmp = cur; cur = nxt; nxt = tmp;
        }
        if (t == 0) pv[0][0] = 128 + g;
        __syncthreads();

        int cnt = 1, msb = 128, sel = 0;
        for (int lvl = 0; lvl < 4; lvl++) {              // levels 9..12
            const int nch = cnt * 2;
            for (int cb = 0; cb < nch; cb += 4) {
                const int c = cb + l;
                if (c < nch) {
                    const int par = c >> 1;
                    const int b   = c & 1;
                    const int pc  = pv[sel][par] + (b + 1) * msb;
                    const float* Qp = b ? Q1s : Q0s;
                    const float* vp = cur + par * 128;
                    float a0 = 0.f, a1 = 0.f, a2 = 0.f, a3 = 0.f;
#pragma unroll
                    for (int i = 0; i < 128; i += 4) {
                        const float4 vv = *(const float4*)(vp + i);
                        a0 += vv.x * Qp[(i + 0) * 128 + j];
                        a1 += vv.y * Qp[(i + 1) * 128 + j];
                        a2 += vv.z * Qp[(i + 2) * 128 + j];
                        a3 += vv.w * Qp[(i + 3) * 128 + j];
                    }
                    const float acc = (a0 + a1) + (a2 + a3);
                    nxt[c * 128 + j] = acc;
                    g_table[pc * 128 + j] = acc;
                    if (j == 0) pv[sel ^ 1][c] = pc;
                }
            }
            __syncthreads();
            float* tmp = cur; cur = nxt; nxt = tmp;
            sel ^= 1; cnt = nch; msb <<= 1;
        }
    }

    // ============ exit counter + replay-safe flag reset =====================
    __syncthreads();
    __threadfence();
    if (t == 0) {
        if (atomicAdd((unsigned*)&g_flags[64], 1u) == NBLOCKS - 1) {
            g_flags[0]  = 0u;
            g_flags[32] = 0u;
            g_flags[64] = 0u;
            __threadfence();
        }
    }
}

// ---------------------------------------------------------------------------
// Kernel 2: final embedding assembly. One warp per token, float4 streaming
// stores. 128 MB write -> HBM-bound (known 24us).
// ---------------------------------------------------------------------------
__global__ __launch_bounds__(256) void out_kernel(const int* __restrict__ tt,
                                                  const int* __restrict__ tv,
                                                  const int* __restrict__ np,
                                                  const float* __restrict__ ew,
                                                  float* __restrict__ out) {
    const int warp = threadIdx.x >> 5;
    const int lane = threadIdx.x & 31;
    const int tok  = blockIdx.x * 8 + warp;      // < 131072

    const int ty  = tt[tok];
    const int val = tv[tok];
    const int pos = np[tok];

    const float4 pv4 = *(const float4*)(g_table + pos * 128 + lane * 4);

    float4 cv;
    if (ty == 4) {
        int idx = val < 0 ? 0 : (val > 4095 ? 4095 : val);
        cv = *(const float4*)(g_table + idx * 128 + lane * 4);
    } else if (ty == 1) {
        cv = *(const float4*)(ew + (val + 1) * 128 + lane * 4);
    } else if (ty == 2) {
        cv = *(const float4*)(ew + (val + 5) * 128 + lane * 4);
    } else if (ty == 0) {
        cv = *(const float4*)(ew + lane * 4);
    } else if (ty == 3 && val == -1) {
        cv = *(const float4*)(ew + 10 * 128 + lane * 4);
    } else {
        cv = make_float4(0.f, 0.f, 0.f, 0.f);
    }

    float* o = out + (size_t)tok * 256;
    __stcs((float4*)(o + lane * 4), cv);
    __stcs((float4*)(o + 128 + lane * 4), pv4);
}

// ---------------------------------------------------------------------------
extern "C" void kernel_launch(void* const* d_in, const int* in_sizes, int n_in,
                              void* d_out, int out_size) {
    const int*   tt    = (const int*)d_in[0];   // token_types   [32,4096]
    const int*   tv    = (const int*)d_in[1];   // token_values  [32,4096]
    const int*   np    = (const int*)d_in[2];   // node_positions[32,4096]
    const float* prim  = (const float*)d_in[3]; // primitives    [2,128,128]
    const float* ident = (const float*)d_in[4]; // identity      [1,128]
    const float* ew    = (const float*)d_in[5]; // embed_weight  [11,128]
    float* out = (float*)d_out;

    const int mega_smem = TBL_SMEM_FLOATS * (int)sizeof(float);   // 147456 B
    cudaFuncSetAttribute(mega_kernel, cudaFuncAttributeMaxDynamicSharedMemorySize, mega_smem);

    mega_kernel<<<NBLOCKS, 512, mega_smem>>>(prim, ident);
    out_kernel<<<16384, 256>>>(tt, tv, np, ew, out);
}

// round 16
// speedup vs baseline: 1.8335x; 1.8335x over previous
#include <cuda_runtime.h>
#include <cuda_bf16.h>

// Scratch (no allocations allowed -> __device__ globals)
__device__ float g_LU[2][128 * 128];     // LU factors of (I - A/2), row-major
__device__ float g_QT[2][128 * 128];     // QT[m][j*128+i] = Q[j][i]
__device__ float g_table[4096 * 128];    // pathemb table for every position value

// Inter-block phase counters, 128B apart. Zero at load; reset each call by the
// last block through the exit counter -> replay-safe.
__device__ volatile unsigned g_flags[3 * 32];  // [0]=c1 lu, [32]=c2 solve, [64]=exit

#define LU_PITCH 129
#define NBLOCKS  128
#define TBL_SMEM_FLOATS (2 * 16384 + 2 * 2048)   // 144 KB dynamic

__device__ __forceinline__ void poll_ge(int idx, unsigned tgt) {
    while (g_flags[idx] < tgt) {}
}

// ---------------------------------------------------------------------------
// Mega preproc kernel: twin-rank-2 LU (blk 0-1, 32 barriers) -> solve
// (blk 0-15) -> table (all). 128 blocks, 1/SM (144KB smem), all resident.
// ---------------------------------------------------------------------------
__global__ __launch_bounds__(512, 1) void mega_kernel(const float* __restrict__ X,
                                                      const float* __restrict__ identity) {
    extern __shared__ float sm[];
    // staging (double-buffered): 4 pivot columns + 4 pivot rows (pre-step values)
    __shared__ float C0[2][128], C1[2][128], C2[2][128], C3[2][128];
    __shared__ float R0[2][128], R1[2][128], R2[2][128], R3[2][128];
    __shared__ int   pv[2][16];

    const int blk  = blockIdx.x;
    const int t    = threadIdx.x;
    const int tr   = t & 31;          // lane
    const int w    = t >> 5;          // warp id (0..15): owns columns 8w..8w+7
    const unsigned FULL = 0xffffffffu;

    // ============ Phase 1: twin-rank-2 LU (32 barriers, 4 cols each) ========
    if (blk < 2) {
        const int m = blk;
        const float* Xm = X + m * 128 * 128;
        float* Xs = sm;                                  // 128*129

        for (int idx = t; idx < 128 * 128; idx += 512)
            Xs[(idx >> 7) * LU_PITCH + (idx & 127)] = Xm[idx];
        __syncthreads();

        // init M = I - 0.5*(tril(X) - tril(X)^T)
        float reg[4][8];
#pragma unroll
        for (int s = 0; s < 4; s++) {
            const int r = tr + 32 * s;
#pragma unroll
            for (int q = 0; q < 8; q++) {
                const int c = 8 * w + q;
                float a = (r > c) ? Xs[r * LU_PITCH + c]
                        : ((r < c) ? -Xs[c * LU_PITCH + r] : 0.0f);
                reg[s][q] = ((r == c) ? 1.0f : 0.0f) - 0.5f * a;
            }
        }

        // stage pivot group 0 (cols 0-3, rows 0-3) into buffer 0
        if (w == 0) {
#pragma unroll
            for (int s = 0; s < 4; s++) {
                C0[0][tr + 32 * s] = reg[s][0];
                C1[0][tr + 32 * s] = reg[s][1];
                C2[0][tr + 32 * s] = reg[s][2];
                C3[0][tr + 32 * s] = reg[s][3];
            }
        }
        if (tr == 0) { for (int q = 0; q < 8; q++) R0[0][8 * w + q] = reg[0][q]; }
        if (tr == 1) { for (int q = 0; q < 8; q++) R1[0][8 * w + q] = reg[0][q]; }
        if (tr == 2) { for (int q = 0; q < 8; q++) R2[0][8 * w + q] = reg[0][q]; }
        if (tr == 3) { for (int q = 0; q < 8; q++) R3[0][8 * w + q] = reg[0][q]; }

        for (int kp = 0; kp < 32; kp++) {
            __syncthreads();
            const int p = kp & 1;
            const int k = 4 * kp;

            if (8 * w + 7 >= k) {                        // warp-uniform dead skip
                // ======== sub-step A: rank-2 on pair (k, k+1) — R13 body ====
                const float aA = R0[p][k];
                const float bA = R0[p][k + 1];
                const float cA = R1[p][k];
                const float dA = R1[p][k + 1];
                const float invaA  = 1.0f / aA;
                const float tA     = cA * invaA;         // L[k+1,k]
                const float tdA    = dA - tA * bA;       // U[k+1,k+1]
                const float invtdA = 1.0f / tdA;

                float u1[8], u2[8];
#pragma unroll
                for (int q = 0; q < 8; q++) {
                    u1[q] = R0[p][8 * w + q];
                    u2[q] = R1[p][8 * w + q] - tA * u1[q];
                }

                // -------- corrections for sub-step B's pivot data (scalars) --
                // rows k+2,k+3 multipliers w.r.t. pair A:
                const float lam1 = C0[p][k + 2] * invaA;
                const float lam2 = (C1[p][k + 2] - lam1 * bA) * invtdA;
                const float mu1  = C0[p][k + 3] * invaA;
                const float mu2  = (C1[p][k + 3] - mu1 * bA) * invtdA;
                // pair-A u-values at columns k+2, k+3:
                const float u1k2 = R0[p][k + 2], u2k2 = R1[p][k + 2] - tA * u1k2;
                const float u1k3 = R0[p][k + 3], u2k3 = R1[p][k + 3] - tA * u1k3;

                // post-A rows k+2,k+3 over this warp's columns:
                float u1p[8], u2p[8];                    // raw; B-scalars below
#pragma unroll
                for (int q = 0; q < 8; q++) {
                    u1p[q] = R2[p][8 * w + q] - lam1 * u1[q] - lam2 * u2[q];
                    u2p[q] = R3[p][8 * w + q] - mu1 * u1[q] - mu2 * u2[q];
                }

                // -------- A: per-row multipliers + update (keep mA for B) ----
                float mA1[4], mA2[4];
#pragma unroll
                for (int s = 0; s < 4; s++) {
                    const int r = tr + 32 * s;
                    if (r > k + 1) {
                        const float l1 = C0[p][r] * invaA;
                        const float l2 = (C1[p][r] - l1 * bA) * invtdA;
                        mA1[s] = l1; mA2[s] = l2;
#pragma unroll
                        for (int q = 0; q < 8; q++) {
                            const int cc = 8 * w + q;
                            if (cc > k + 1)       reg[s][q] -= l1 * u1[q] + l2 * u2[q];
                            else if (cc == k)     reg[s][q]  = l1;
                            else if (cc == k + 1) reg[s][q]  = l2;
                        }
                    } else {
                        mA1[s] = 0.0f; mA2[s] = 0.0f;
                        if (r == k + 1) {
#pragma unroll
                            for (int q = 0; q < 8; q++) {
                                const int cc = 8 * w + q;
                                if (cc >= k + 1)  reg[s][q] -= tA * u1[q];
                                else if (cc == k) reg[s][q]  = tA;
                            }
                        }
                    }
                }

                // ======== sub-step B: rank-2 on pair (k+2, k+3) =============
                // pivot scalars from corrected rows (all scalar algebra):
                const float aB = R2[p][k + 2] - lam1 * u1k2 - lam2 * u2k2;
                const float bB = R2[p][k + 3] - lam1 * u1k3 - lam2 * u2k3;
                const float cB = R3[p][k + 2] - mu1 * u1k2 - mu2 * u2k2;
                const float dB = R3[p][k + 3] - mu1 * u1k3 - mu2 * u2k3;
                const float invaB  = 1.0f / aB;
                const float tB     = cB * invaB;         // L[k+3,k+2]
                const float tdB    = dB - tB * bB;
                const float invtdB = 1.0f / tdB;
#pragma unroll
                for (int q = 0; q < 8; q++)
                    u2p[q] -= tB * u1p[q];               // finalize B's second U-row

#pragma unroll
                for (int s = 0; s < 4; s++) {
                    const int r = tr + 32 * s;
                    if (r > k + 3) {
                        // post-A columns k+2,k+3 at row r (own mA corrections)
                        const float c2p = C2[p][r] - mA1[s] * u1k2 - mA2[s] * u2k2;
                        const float c3p = C3[p][r] - mA1[s] * u1k3 - mA2[s] * u2k3;
                        const float l1 = c2p * invaB;
                        const float l2 = (c3p - l1 * bB) * invtdB;
#pragma unroll
                        for (int q = 0; q < 8; q++) {
                            const int cc = 8 * w + q;
                            if (cc > k + 3)       reg[s][q] -= l1 * u1p[q] + l2 * u2p[q];
                            else if (cc == k + 2) reg[s][q]  = l1;
                            else if (cc == k + 3) reg[s][q]  = l2;
                        }
                    } else if (r == k + 3) {
#pragma unroll
                        for (int q = 0; q < 8; q++) {
                            const int cc = 8 * w + q;
                            if (cc >= k + 3)      reg[s][q] -= tB * u1p[q];
                            else if (cc == k + 2) reg[s][q]  = tB;
                        }
                    }
                }

                // ---- stage next pivot group (cols/rows k+4..k+7) ----
                if (kp < 31) {
                    const int kn = k + 4;
                    if (w == (kn >> 3)) {                // column owner warp
                        const int qn = kn & 7;           // 0 or 4
#pragma unroll
                        for (int s = 0; s < 4; s++) {
                            float v0, v1, v2, v3;
                            if (qn == 0) { v0 = reg[s][0]; v1 = reg[s][1]; v2 = reg[s][2]; v3 = reg[s][3]; }
                            else         { v0 = reg[s][4]; v1 = reg[s][5]; v2 = reg[s][6]; v3 = reg[s][7]; }
                            C0[p ^ 1][tr + 32 * s] = v0;
                            C1[p ^ 1][tr + 32 * s] = v1;
                            C2[p ^ 1][tr + 32 * s] = v2;
                            C3[p ^ 1][tr + 32 * s] = v3;
                        }
                    }
#pragma unroll
                    for (int i = 0; i < 4; i++) {
                        if (tr == ((kn + i) & 31)) {     // row kn+i owner lane
                            const int sn = (kn + i) >> 5;
#pragma unroll
                            for (int q = 0; q < 8; q++) {
                                float v = reg[0][q];
#pragma unroll
                                for (int ss = 1; ss < 4; ss++)
                                    if (ss == sn) v = reg[ss][q];
                                if (i == 0)      R0[p ^ 1][8 * w + q] = v;
                                else if (i == 1) R1[p ^ 1][8 * w + q] = v;
                                else if (i == 2) R2[p ^ 1][8 * w + q] = v;
                                else             R3[p ^ 1][8 * w + q] = v;
                            }
                        }
                    }
                }
            }
        }
        __syncthreads();
#pragma unroll
        for (int s = 0; s < 4; s++) {
            const int r = tr + 32 * s;
#pragma unroll
            for (int q = 0; q < 8; q++)
                Xs[r * LU_PITCH + 8 * w + q] = reg[s][q];
        }
        __syncthreads();
        for (int idx = t; idx < 128 * 128; idx += 512)
            g_LU[m][idx] = Xs[(idx >> 7) * LU_PITCH + (idx & 127)];
        __syncthreads();
        __threadfence();
        if (t == 0) atomicAdd((unsigned*)&g_flags[0], 1u);      // c1++
    }

    // =========================== Phase 2: solve =============================
    if (blk < 16) {
        if (t == 0) poll_ge(0, 2u);
        __syncthreads();
        __threadfence();

        const int m = blk >> 3;
        const int j = ((blk & 7) << 4) + w;              // 16 RHS per block
        const float* Xm  = X + m * 128 * 128;
        const float* LUg = g_LU[m];
        float* LUs   = sm;                               // 128*129
        float* rdiag = sm + 128 * LU_PITCH;              // 128

        for (int idx = t; idx < 128 * 128; idx += 512)
            LUs[(idx >> 7) * LU_PITCH + (idx & 127)] = LUg[idx];
        if (t < 128) rdiag[t] = 1.0f / LUg[t * 128 + t];
        __syncthreads();

        const int lane = tr;
        float y0, y1, y2, y3;
        {
            const int i0 = lane, i1 = lane + 32, i2 = lane + 64, i3 = lane + 96;
            float a0 = (i0 > j) ? Xm[i0 * 128 + j] : ((i0 < j) ? -Xm[j * 128 + i0] : 0.0f);
            float a1 = (i1 > j) ? Xm[i1 * 128 + j] : ((i1 < j) ? -Xm[j * 128 + i1] : 0.0f);
            float a2 = (i2 > j) ? Xm[i2 * 128 + j] : ((i2 < j) ? -Xm[j * 128 + i2] : 0.0f);
            float a3 = (i3 > j) ? Xm[i3 * 128 + j] : ((i3 < j) ? -Xm[j * 128 + i3] : 0.0f);
            y0 = ((i0 == j) ? 1.0f : 0.0f) + 0.5f * a0;
            y1 = ((i1 == j) ? 1.0f : 0.0f) + 0.5f * a1;
            y2 = ((i2 == j) ? 1.0f : 0.0f) + 0.5f * a2;
            y3 = ((i3 == j) ? 1.0f : 0.0f) + 0.5f * a3;
        }

        // forward: L z = r (unit lower)
#pragma unroll 4
        for (int kk = 0; kk < 32; kk++) {
            const float yk = __shfl_sync(FULL, y0, kk);
            const float* col = LUs + kk;
            if (lane > kk) y0 -= col[lane * LU_PITCH] * yk;
            y1 -= col[(lane + 32) * LU_PITCH] * yk;
            y2 -= col[(lane + 64) * LU_PITCH] * yk;
            y3 -= col[(lane + 96) * LU_PITCH] * yk;
        }
#pragma unroll 4
        for (int kk = 0; kk < 32; kk++) {
            const float yk = __shfl_sync(FULL, y1, kk);
            const float* col = LUs + 32 + kk;
            if (lane > kk) y1 -= col[(lane + 32) * LU_PITCH] * yk;
            y2 -= col[(lane + 64) * LU_PITCH] * yk;
            y3 -= col[(lane + 96) * LU_PITCH] * yk;
        }
#pragma unroll 4
        for (int kk = 0; kk < 32; kk++) {
            const float yk = __shfl_sync(FULL, y2, kk);
            const float* col = LUs + 64 + kk;
            if (lane > kk) y2 -= col[(lane + 64) * LU_PITCH] * yk;
            y3 -= col[(lane + 96) * LU_PITCH] * yk;
        }
#pragma unroll 4
        for (int kk = 0; kk < 31; kk++) {
            const float yk = __shfl_sync(FULL, y3, kk);
            if (lane > kk) y3 -= LUs[(lane + 96) * LU_PITCH + 96 + kk] * yk;
        }
        // backward: U q = z
#pragma unroll 4
        for (int kk = 31; kk >= 0; kk--) {
            const int k = 96 + kk;
            const float yk = __shfl_sync(FULL, y3, kk) * rdiag[k];
            if (lane == kk) y3 = yk;
            else if (lane < kk) y3 -= LUs[(lane + 96) * LU_PITCH + k] * yk;
            y0 -= LUs[lane * LU_PITCH + k] * yk;
            y1 -= LUs[(lane + 32) * LU_PITCH + k] * yk;
            y2 -= LUs[(lane + 64) * LU_PITCH + k] * yk;
        }
#pragma unroll 4
        for (int kk = 31; kk >= 0; kk--) {
            const int k = 64 + kk;
            const float yk = __shfl_sync(FULL, y2, kk) * rdiag[k];
            if (lane == kk) y2 = yk;
            else if (lane < kk) y2 -= LUs[(lane + 64) * LU_PITCH + k] * yk;
            y0 -= LUs[lane * LU_PITCH + k] * yk;
            y1 -= LUs[(lane + 32) * LU_PITCH + k] * yk;
        }
#pragma unroll 4
        for (int kk = 31; kk >= 0; kk--) {
            const int k = 32 + kk;
            const float yk = __shfl_sync(FULL, y1, kk) * rdiag[k];
            if (lane == kk) y1 = yk;
            else if (lane < kk) y1 -= LUs[(lane + 32) * LU_PITCH + k] * yk;
            y0 -= LUs[lane * LU_PITCH + k] * yk;
        }
#pragma unroll 4
        for (int kk = 31; kk >= 0; kk--) {
            const float yk = __shfl_sync(FULL, y0, kk) * rdiag[kk];
            if (lane == kk) y0 = yk;
            else if (lane < kk) y0 -= LUs[lane * LU_PITCH + kk] * yk;
        }
        float* dst = g_QT[m] + j * 128 + lane;
        dst[0] = y0; dst[32] = y1; dst[64] = y2; dst[96] = y3;

        __syncthreads();
        __threadfence();
        if (t == 0) atomicAdd((unsigned*)&g_flags[32], 1u);     // c2++
    }

    // =========================== Phase 3: table =============================
    if (t == 0) poll_ge(32, 16u);
    __syncthreads();
    __threadfence();

    {
        float* Q0s  = sm;
        float* Q1s  = sm + 16384;
        float* bufA = sm + 32768;
        float* bufB = sm + 34816;
        const int g = blk;
        const int l = t >> 7;
        const int j = t & 127;

        {
            const float4* src = (const float4*)g_QT;
            float4* dst = (float4*)sm;
            for (int i = t; i < 8192; i += 512) dst[i] = src[i];
        }
        if (t < 128) bufA[j] = identity[j];
        if (g == 0 && t < 128) {
            g_table[0 + j]   = identity[j];
            g_table[128 + j] = identity[j];
        }
        __syncthreads();

        float* cur = bufA;
        float* nxt = bufB;
        for (int d = 0; d < 7; d++) {                    // root path: levels 2..8
            if (t < 128) {
                const int b = (g >> d) & 1;
                const float* Qp = b ? Q1s : Q0s;
                float a0 = 0.f, a1 = 0.f, a2 = 0.f, a3 = 0.f;
                for (int i = 0; i < 128; i += 4) {
                    const float4 vv = *(const float4*)(cur + i);
                    a0 += vv.x * Qp[(i + 0) * 128 + j];
                    a1 += vv.y * Qp[(i + 1) * 128 + j];
                    a2 += vv.z * Qp[(i + 2) * 128 + j];
                    a3 += vv.w * Qp[(i + 3) * 128 + j];
                }
                const float acc = (a0 + a1) + (a2 + a3);
                nxt[j] = acc;
                const int p = (g & ((2 << d) - 1)) | (2 << d);
                g_table[p * 128 + j] = acc;
            }
            __syncthreads();
            float* tmp = cur; cur = nxt; nxt = tmp;
        }
        if (t == 0) pv[0][0] = 128 + g;
        __syncthreads();

        int cnt = 1, msb = 128, sel = 0;
        for (int lvl = 0; lvl < 4; lvl++) {              // levels 9..12
            const int nch = cnt * 2;
            for (int cb = 0; cb < nch; cb += 4) {
                const int c = cb + l;
                if (c < nch) {
                    const int par = c >> 1;
                    const int b   = c & 1;
                    const int pc  = pv[sel][par] + (b + 1) * msb;
                    const float* Qp = b ? Q1s : Q0s;
                    const float* vp = cur + par * 128;
                    float a0 = 0.f, a1 = 0.f, a2 = 0.f, a3 = 0.f;
                    for (int i = 0; i < 128; i += 4) {
                        const float4 vv = *(const float4*)(vp + i);
                        a0 += vv.x * Qp[(i + 0) * 128 + j];
                        a1 += vv.y * Qp[(i + 1) * 128 + j];
                        a2 += vv.z * Qp[(i + 2) * 128 + j];
                        a3 += vv.w * Qp[(i + 3) * 128 + j];
                    }
                    const float acc = (a0 + a1) + (a2 + a3);
                    nxt[c * 128 + j] = acc;
                    g_table[pc * 128 + j] = acc;
                    if (j == 0) pv[sel ^ 1][c] = pc;
                }
            }
            __syncthreads();
            float* tmp = cur; cur = nxt; nxt = tmp;
            sel ^= 1; cnt = nch; msb <<= 1;
        }
    }

    // ============ exit counter + replay-safe flag reset =====================
    __syncthreads();
    __threadfence();
    if (t == 0) {
        if (atomicAdd((unsigned*)&g_flags[64], 1u) == NBLOCKS - 1) {
            g_flags[0]  = 0u;
            g_flags[32] = 0u;
            g_flags[64] = 0u;
            __threadfence();
        }
    }
}

// ---------------------------------------------------------------------------
// Kernel 2: final embedding assembly. One warp per token, float4 streaming
// stores. 128 MB write -> HBM-bound (known ~24us).
// ---------------------------------------------------------------------------
__global__ __launch_bounds__(256) void out_kernel(const int* __restrict__ tt,
                                                  const int* __restrict__ tv,
                                                  const int* __restrict__ np,
                                                  const float* __restrict__ ew,
                                                  float* __restrict__ out) {
    const int warp = threadIdx.x >> 5;
    const int lane = threadIdx.x & 31;
    const int tok  = blockIdx.x * 8 + warp;      // < 131072

    const int ty  = tt[tok];
    const int val = tv[tok];
    const int pos = np[tok];

    const float4 pv4 = *(const float4*)(g_table + pos * 128 + lane * 4);

    float4 cv;
    if (ty == 4) {
        int idx = val < 0 ? 0 : (val > 4095 ? 4095 : val);
        cv = *(const float4*)(g_table + idx * 128 + lane * 4);
    } else if (ty == 1) {
        cv = *(const float4*)(ew + (val + 1) * 128 + lane * 4);
    } else if (ty == 2) {
        cv = *(const float4*)(ew + (val + 5) * 128 + lane * 4);
    } else if (ty == 0) {
        cv = *(const float4*)(ew + lane * 4);
    } else if (ty == 3 && val == -1) {
        cv = *(const float4*)(ew + 10 * 128 + lane * 4);
    } else {
        cv = make_float4(0.f, 0.f, 0.f, 0.f);
    }

    float* o = out + (size_t)tok * 256;
    __stcs((float4*)(o + lane * 4), cv);
    __stcs((float4*)(o + 128 + lane * 4), pv4);
}

// ---------------------------------------------------------------------------
extern "C" void kernel_launch(void* const* d_in, const int* in_sizes, int n_in,
                              void* d_out, int out_size) {
    const int*   tt    = (const int*)d_in[0];   // token_types   [32,4096]
    const int*   tv    = (const int*)d_in[1];   // token_values  [32,4096]
    const int*   np    = (const int*)d_in[2];   // node_positions[32,4096]
    const float* prim  = (const float*)d_in[3]; // primitives    [2,128,128]
    const float* ident = (const float*)d_in[4]; // identity      [1,128]
    const float* ew    = (const float*)d_in[5]; // embed_weight  [11,128]
    float* out = (float*)d_out;

    const int mega_smem = TBL_SMEM_FLOATS * (int)sizeof(float);   // 147456 B
    cudaFuncSetAttribute(mega_kernel, cudaFuncAttributeMaxDynamicSharedMemorySize, mega_smem);

    mega_kernel<<<NBLOCKS, 512, mega_smem>>>(prim, ident);
    out_kernel<<<16384, 256>>>(tt, tv, np, ew, out);
}

// round 17
// speedup vs baseline: 2.1788x; 1.1883x over previous
#include <cuda_runtime.h>
#include <cuda_bf16.h>

// Scratch (no allocations allowed -> __device__ globals)
__device__ float g_LU[2][128 * 128];     // LU factors of (I - A/2), row-major
__device__ float g_QT[2][128 * 128];     // QT[m][j*128+i] = Q[j][i]
__device__ float g_table[4096 * 128];    // pathemb table for every position value

// Inter-block phase counters, 128B apart. Zero at load; reset each call by the
// last block through the exit counter -> replay-safe.
__device__ volatile unsigned g_flags[3 * 32];  // [0]=c1 lu, [32]=c2 solve, [64]=exit

#define LU_PITCH 129
#define NBLOCKS  128
#define TBL_SMEM_FLOATS (2 * 16384 + 2 * 2048)   // 144 KB dynamic

__device__ __forceinline__ void poll_ge(int idx, unsigned tgt) {
    while (g_flags[idx] < tgt) {}
}

// Blocked LU outer step: panel width 8 (warp iC's own column block), then
// trsm + rank-8 Schur by warps > iC. ALL register indices compile-time
// (constexpr iC; q/s loops unrolled with predicated q==j / q>j forms).
#define LU_STEP(ii)                                                            \
{                                                                              \
    constexpr int iC = (ii);                                                   \
    constexpr int kC = 8 * iC;                                                 \
    constexpr int aC = iC >> 2;   /* register slot holding rows kC..kC+7 */    \
    constexpr int bC = iC & 3;    /* lane group 8bC..8bC+7 holds them   */     \
    if (w == iC) {                                                             \
        _Pragma("unroll")                                                      \
        for (int j = 0; j < 8; j++) {                                          \
            float pj[8]; float pvv = 0.f;                                      \
            _Pragma("unroll")                                                  \
            for (int q = 0; q < 8; q++) {                                      \
                pj[q] = __shfl_sync(FULL, reg[aC][q], 8 * bC + j);             \
                if (q == j) pvv = pj[q];                                       \
            }                                                                  \
            const float inv = 1.0f / pvv;                                      \
            _Pragma("unroll")                                                  \
            for (int s = 0; s < 4; s++) {                                      \
                const int r = tr + 32 * s;                                     \
                if (r > kC + j) {                                              \
                    float rj = 0.f;                                            \
                    _Pragma("unroll")                                          \
                    for (int q = 0; q < 8; q++) { if (q == j) rj = reg[s][q]; }\
                    const float l = rj * inv;                                  \
                    _Pragma("unroll")                                          \
                    for (int q = 0; q < 8; q++) {                              \
                        if (q > j)       reg[s][q] -= l * pj[q];               \
                        else if (q == j) reg[s][q]  = l;                       \
                    }                                                          \
                }                                                              \
            }                                                                  \
        }                                                                      \
        _Pragma("unroll")                                                      \
        for (int s = 0; s < 4; s++) {                                          \
            _Pragma("unroll")                                                  \
            for (int q = 0; q < 8; q++)                                        \
                Pst[iC & 1][(tr + 32 * s) * 9 + q] = reg[s][q];                \
        }                                                                      \
    }                                                                          \
    __syncthreads();                                                           \
    if (w > iC) {                                                              \
        const float* Pb = Pst[iC & 1];                                         \
        _Pragma("unroll")                                                      \
        for (int j2 = 0; j2 < 7; j2++) {    /* trsm rows kC..kC+7 */           \
            float uu[8];                                                       \
            _Pragma("unroll")                                                  \
            for (int q = 0; q < 8; q++)                                        \
                uu[q] = __shfl_sync(FULL, reg[aC][q], 8 * bC + j2);            \
            if (tr > 8 * bC + j2 && tr < 8 * bC + 8) {                         \
                const float lv = Pb[(kC + tr - 8 * bC) * 9 + j2];              \
                _Pragma("unroll")                                              \
                for (int q = 0; q < 8; q++) reg[aC][q] -= lv * uu[q];          \
            }                                                                  \
        }                                                                      \
        _Pragma("unroll")                                                      \
        for (int j = 0; j < 8; j++) {       /* rank-8 Schur, rows > kC+7 */    \
            float uu[8];                                                       \
            _Pragma("unroll")                                                  \
            for (int q = 0; q < 8; q++)                                        \
                uu[q] = __shfl_sync(FULL, reg[aC][q], 8 * bC + j);             \
            _Pragma("unroll")                                                  \
            for (int s = 0; s < 4; s++) {                                      \
                const int r = tr + 32 * s;                                     \
                if (r > kC + 7) {                                              \
                    const float lv = Pb[r * 9 + j];                            \
                    _Pragma("unroll")                                          \
                    for (int q = 0; q < 8; q++) reg[s][q] -= lv * uu[q];       \
                }                                                              \
            }                                                                  \
        }                                                                      \
    }                                                                          \
}

// ---------------------------------------------------------------------------
// Mega preproc kernel: blocked LU (blk 0-1, 16 barriers) -> solve (blk 0-15)
// -> table (all). 128 blocks, 1/SM (144KB smem), all resident -> spin-safe.
// ---------------------------------------------------------------------------
__global__ __launch_bounds__(512, 1) void mega_kernel(const float* __restrict__ X,
                                                      const float* __restrict__ identity) {
    extern __shared__ float sm[];
    __shared__ float Pst[2][128 * 9];      // double-buffered panel stage (pitch 9)
    __shared__ int   pv[2][16];

    const int blk  = blockIdx.x;
    const int t    = threadIdx.x;
    const int tr   = t & 31;          // lane
    const int w    = t >> 5;          // warp id (0..15): owns columns 8w..8w+7
    const unsigned FULL = 0xffffffffu;

    // ================= Phase 1: blocked LU (16 barriers) ====================
    if (blk < 2) {
        const int m = blk;
        const float* Xm = X + m * 128 * 128;
        float* Xs = sm;                                  // 128*129

        for (int idx = t; idx < 128 * 128; idx += 512)
            Xs[(idx >> 7) * LU_PITCH + (idx & 127)] = Xm[idx];
        __syncthreads();

        // init M = I - 0.5*(tril(X) - tril(X)^T)
        float reg[4][8];
#pragma unroll
        for (int s = 0; s < 4; s++) {
            const int r = tr + 32 * s;
#pragma unroll
            for (int q = 0; q < 8; q++) {
                const int c = 8 * w + q;
                float a = (r > c) ? Xs[r * LU_PITCH + c]
                        : ((r < c) ? -Xs[c * LU_PITCH + r] : 0.0f);
                reg[s][q] = ((r == c) ? 1.0f : 0.0f) - 0.5f * a;
            }
        }
        __syncthreads();

        LU_STEP(0);  LU_STEP(1);  LU_STEP(2);  LU_STEP(3);
        LU_STEP(4);  LU_STEP(5);  LU_STEP(6);  LU_STEP(7);
        LU_STEP(8);  LU_STEP(9);  LU_STEP(10); LU_STEP(11);
        LU_STEP(12); LU_STEP(13); LU_STEP(14); LU_STEP(15);

        __syncthreads();
#pragma unroll
        for (int s = 0; s < 4; s++) {
            const int r = tr + 32 * s;
#pragma unroll
            for (int q = 0; q < 8; q++)
                Xs[r * LU_PITCH + 8 * w + q] = reg[s][q];
        }
        __syncthreads();
        for (int idx = t; idx < 128 * 128; idx += 512)
            g_LU[m][idx] = Xs[(idx >> 7) * LU_PITCH + (idx & 127)];
        __syncthreads();
        __threadfence();
        if (t == 0) atomicAdd((unsigned*)&g_flags[0], 1u);      // c1++
    }

    // =========================== Phase 2: solve =============================
    if (blk < 16) {
        if (t == 0) poll_ge(0, 2u);
        __syncthreads();
        __threadfence();

        const int m = blk >> 3;
        const int j = ((blk & 7) << 4) + w;              // 16 RHS per block
        const float* Xm  = X + m * 128 * 128;
        const float* LUg = g_LU[m];
        float* LUs   = sm;                               // 128*129
        float* rdiag = sm + 128 * LU_PITCH;              // 128

        for (int idx = t; idx < 128 * 128; idx += 512)
            LUs[(idx >> 7) * LU_PITCH + (idx & 127)] = LUg[idx];
        if (t < 128) rdiag[t] = 1.0f / LUg[t * 128 + t];
        __syncthreads();

        const int lane = tr;
        float y0, y1, y2, y3;
        {
            const int i0 = lane, i1 = lane + 32, i2 = lane + 64, i3 = lane + 96;
            float a0 = (i0 > j) ? Xm[i0 * 128 + j] : ((i0 < j) ? -Xm[j * 128 + i0] : 0.0f);
            float a1 = (i1 > j) ? Xm[i1 * 128 + j] : ((i1 < j) ? -Xm[j * 128 + i1] : 0.0f);
            float a2 = (i2 > j) ? Xm[i2 * 128 + j] : ((i2 < j) ? -Xm[j * 128 + i2] : 0.0f);
            float a3 = (i3 > j) ? Xm[i3 * 128 + j] : ((i3 < j) ? -Xm[j * 128 + i3] : 0.0f);
            y0 = ((i0 == j) ? 1.0f : 0.0f) + 0.5f * a0;
            y1 = ((i1 == j) ? 1.0f : 0.0f) + 0.5f * a1;
            y2 = ((i2 == j) ? 1.0f : 0.0f) + 0.5f * a2;
            y3 = ((i3 == j) ? 1.0f : 0.0f) + 0.5f * a3;
        }

        // forward: L z = r (unit lower)
#pragma unroll 4
        for (int kk = 0; kk < 32; kk++) {
            const float yk = __shfl_sync(FULL, y0, kk);
            const float* col = LUs + kk;
            if (lane > kk) y0 -= col[lane * LU_PITCH] * yk;
            y1 -= col[(lane + 32) * LU_PITCH] * yk;
            y2 -= col[(lane + 64) * LU_PITCH] * yk;
            y3 -= col[(lane + 96) * LU_PITCH] * yk;
        }
#pragma unroll 4
        for (int kk = 0; kk < 32; kk++) {
            const float yk = __shfl_sync(FULL, y1, kk);
            const float* col = LUs + 32 + kk;
            if (lane > kk) y1 -= col[(lane + 32) * LU_PITCH] * yk;
            y2 -= col[(lane + 64) * LU_PITCH] * yk;
            y3 -= col[(lane + 96) * LU_PITCH] * yk;
        }
#pragma unroll 4
        for (int kk = 0; kk < 32; kk++) {
            const float yk = __shfl_sync(FULL, y2, kk);
            const float* col = LUs + 64 + kk;
            if (lane > kk) y2 -= col[(lane + 64) * LU_PITCH] * yk;
            y3 -= col[(lane + 96) * LU_PITCH] * yk;
        }
#pragma unroll 4
        for (int kk = 0; kk < 31; kk++) {
            const float yk = __shfl_sync(FULL, y3, kk);
            if (lane > kk) y3 -= LUs[(lane + 96) * LU_PITCH + 96 + kk] * yk;
        }
        // backward: U q = z
#pragma unroll 4
        for (int kk = 31; kk >= 0; kk--) {
            const int k = 96 + kk;
            const float yk = __shfl_sync(FULL, y3, kk) * rdiag[k];
            if (lane == kk) y3 = yk;
            else if (lane < kk) y3 -= LUs[(lane + 96) * LU_PITCH + k] * yk;
            y0 -= LUs[lane * LU_PITCH + k] * yk;
            y1 -= LUs[(lane + 32) * LU_PITCH + k] * yk;
            y2 -= LUs[(lane + 64) * LU_PITCH + k] * yk;
        }
#pragma unroll 4
        for (int kk = 31; kk >= 0; kk--) {
            const int k = 64 + kk;
            const float yk = __shfl_sync(FULL, y2, kk) * rdiag[k];
            if (lane == kk) y2 = yk;
            else if (lane < kk) y2 -= LUs[(lane + 64) * LU_PITCH + k] * yk;
            y0 -= LUs[lane * LU_PITCH + k] * yk;
            y1 -= LUs[(lane + 32) * LU_PITCH + k] * yk;
        }
#pragma unroll 4
        for (int kk = 31; kk >= 0; kk--) {
            const int k = 32 + kk;
            const float yk = __shfl_sync(FULL, y1, kk) * rdiag[k];
            if (lane == kk) y1 = yk;
            else if (lane < kk) y1 -= LUs[(lane + 32) * LU_PITCH + k] * yk;
            y0 -= LUs[lane * LU_PITCH + k] * yk;
        }
#pragma unroll 4
        for (int kk = 31; kk >= 0; kk--) {
            const float yk = __shfl_sync(FULL, y0, kk) * rdiag[kk];
            if (lane == kk) y0 = yk;
            else if (lane < kk) y0 -= LUs[lane * LU_PITCH + kk] * yk;
        }
        float* dst = g_QT[m] + j * 128 + lane;
        dst[0] = y0; dst[32] = y1; dst[64] = y2; dst[96] = y3;

        __syncthreads();
        __threadfence();
        if (t == 0) atomicAdd((unsigned*)&g_flags[32], 1u);     // c2++
    }

    // =========================== Phase 3: table =============================
    if (t == 0) poll_ge(32, 16u);
    __syncthreads();
    __threadfence();

    {
        float* Q0s  = sm;
        float* Q1s  = sm + 16384;
        float* bufA = sm + 32768;
        float* bufB = sm + 34816;
        const int g = blk;
        const int l = t >> 7;
        const int j = t & 127;

        {
            const float4* src = (const float4*)g_QT;
            float4* dst = (float4*)sm;
            for (int i = t; i < 8192; i += 512) dst[i] = src[i];
        }
        if (t < 128) bufA[j] = identity[j];
        if (g == 0 && t < 128) {
            g_table[0 + j]   = identity[j];
            g_table[128 + j] = identity[j];
        }
        __syncthreads();

        float* cur = bufA;
        float* nxt = bufB;
        for (int d = 0; d < 7; d++) {                    // root path: levels 2..8
            if (t < 128) {
                const int b = (g >> d) & 1;
                const float* Qp = b ? Q1s : Q0s;
                float a0 = 0.f, a1 = 0.f, a2 = 0.f, a3 = 0.f;
                for (int i = 0; i < 128; i += 4) {
                    const float4 vv = *(const float4*)(cur + i);
                    a0 += vv.x * Qp[(i + 0) * 128 + j];
                    a1 += vv.y * Qp[(i + 1) * 128 + j];
                    a2 += vv.z * Qp[(i + 2) * 128 + j];
                    a3 += vv.w * Qp[(i + 3) * 128 + j];
                }
                const float acc = (a0 + a1) + (a2 + a3);
                nxt[j] = acc;
                const int p = (g & ((2 << d) - 1)) | (2 << d);
                g_table[p * 128 + j] = acc;
            }
            __syncthreads();
            float* tmp = cur; cur = nxt; nxt = tmp;
        }
        if (t == 0) pv[0][0] = 128 + g;
        __syncthreads();

        int cnt = 1, msb = 128, sel = 0;
        for (int lvl = 0; lvl < 4; lvl++) {              // levels 9..12
            const int nch = cnt * 2;
            for (int cb = 0; cb < nch; cb += 4) {
                const int c = cb + l;
                if (c < nch) {
                    const int par = c >> 1;
                    const int b   = c & 1;
                    const int pc  = pv[sel][par] + (b + 1) * msb;
                    const float* Qp = b ? Q1s : Q0s;
                    const float* vp = cur + par * 128;
                    float a0 = 0.f, a1 = 0.f, a2 = 0.f, a3 = 0.f;
                    for (int i = 0; i < 128; i += 4) {
                        const float4 vv = *(const float4*)(vp + i);
                        a0 += vv.x * Qp[(i + 0) * 128 + j];
                        a1 += vv.y * Qp[(i + 1) * 128 + j];
                        a2 += vv.z * Qp[(i + 2) * 128 + j];
                        a3 += vv.w * Qp[(i + 3) * 128 + j];
                    }
                    const float acc = (a0 + a1) + (a2 + a3);
                    nxt[c * 128 + j] = acc;
                    g_table[pc * 128 + j] = acc;
                    if (j == 0) pv[sel ^ 1][c] = pc;
                }
            }
            __syncthreads();
            float* tmp = cur; cur = nxt; nxt = tmp;
            sel ^= 1; cnt = nch; msb <<= 1;
        }
    }

    // ============ exit counter + replay-safe flag reset =====================
    __syncthreads();
    __threadfence();
    if (t == 0) {
        if (atomicAdd((unsigned*)&g_flags[64], 1u) == NBLOCKS - 1) {
            g_flags[0]  = 0u;
            g_flags[32] = 0u;
            g_flags[64] = 0u;
            __threadfence();
        }
    }
}

// ---------------------------------------------------------------------------
// Kernel 2: final embedding assembly. One warp per token, float4 streaming
// stores. 128 MB write -> HBM-bound (known ~24us).
// ---------------------------------------------------------------------------
__global__ __launch_bounds__(256) void out_kernel(const int* __restrict__ tt,
                                                  const int* __restrict__ tv,
                                                  const int* __restrict__ np,
                                                  const float* __restrict__ ew,
                                                  float* __restrict__ out) {
    const int warp = threadIdx.x >> 5;
    const int lane = threadIdx.x & 31;
    const int tok  = blockIdx.x * 8 + warp;      // < 131072

    const int ty  = tt[tok];
    const int val = tv[tok];
    const int pos = np[tok];

    const float4 pv4 = *(const float4*)(g_table + pos * 128 + lane * 4);

    float4 cv;
    if (ty == 4) {
        int idx = val < 0 ? 0 : (val > 4095 ? 4095 : val);
        cv = *(const float4*)(g_table + idx * 128 + lane * 4);
    } else if (ty == 1) {
        cv = *(const float4*)(ew + (val + 1) * 128 + lane * 4);
    } else if (ty == 2) {
        cv = *(const float4*)(ew + (val + 5) * 128 + lane * 4);
    } else if (ty == 0) {
        cv = *(const float4*)(ew + lane * 4);
    } else if (ty == 3 && val == -1) {
        cv = *(const float4*)(ew + 10 * 128 + lane * 4);
    } else {
        cv = make_float4(0.f, 0.f, 0.f, 0.f);
    }

    float* o = out + (size_t)tok * 256;
    __stcs((float4*)(o + lane * 4), cv);
    __stcs((float4*)(o + 128 + lane * 4), pv4);
}

// ---------------------------------------------------------------------------
extern "C" void kernel_launch(void* const* d_in, const int* in_sizes, int n_in,
                              void* d_out, int out_size) {
    const int*   tt    = (const int*)d_in[0];   // token_types   [32,4096]
    const int*   tv    = (const int*)d_in[1];   // token_values  [32,4096]
    const int*   np    = (const int*)d_in[2];   // node_positions[32,4096]
    const float* prim  = (const float*)d_in[3]; // primitives    [2,128,128]
    const float* ident = (const float*)d_in[4]; // identity      [1,128]
    const float* ew    = (const float*)d_in[5]; // embed_weight  [11,128]
    float* out = (float*)d_out;

    const int mega_smem = TBL_SMEM_FLOATS * (int)sizeof(float);   // 147456 B
    cudaFuncSetAttribute(mega_kernel, cudaFuncAttributeMaxDynamicSharedMemorySize, mega_smem);

    mega_kernel<<<NBLOCKS, 512, mega_smem>>>(prim, ident);
    out_kernel<<<16384, 256>>>(tt, tv, np, ew, out);
}